// round 16
// baseline (speedup 1.0000x reference)
#include <cuda_runtime.h>

// Relativistic charged-particle Lagrangian dynamics — TWO kernels (de-fused).
// R16: R6's architecture (fast kernel with NO fp64 and no function calls ->
// low register pressure; measured ~8us in R6) + R7's fast slow-path (fp64
// adjugate rank-1 deflation pinv, no fp64 div/sqrt, ~2us) replacing R6's
// 101us Jacobi. Counter reset folded into the slow kernel's last block.
// Fast path bits identical to the best-measured rounds: bit-exact XLA H
// (tanh rational approx, cublas fma k-chains, (0.1*A_j)*A_i association,
// const-folded +eta), compensated 2x2 minors, double-single determinant,
// adjugate Cramer, routing at 4*RCOND.

#define RCOND 4.7683716e-6f   /* 10 * 4 * eps(f32): jnp pinv default */
#define MAX_SLOW 262144

__device__ unsigned int g_slow_count = 0u;
__device__ unsigned int g_done_blocks = 0u;
__device__ int g_slow_idx[MAX_SLOW];

// ---------- XLA GPU f32 tanh ----------
__device__ __forceinline__ float xla_tanh(float x) {
    float ax = fabsf(x);
    float xc = fminf(fmaxf(x, -7.90531110763549805f), 7.90531110763549805f);
    float x2 = __fmul_rn(xc, xc);
    float np = -2.76076847742355e-16f;
    np = __fmaf_rn(np, x2, 2.00018790482477e-13f);
    np = __fmaf_rn(np, x2, -8.60467152213735e-11f);
    np = __fmaf_rn(np, x2, 5.12229709037114e-08f);
    np = __fmaf_rn(np, x2, 1.48572235717979e-05f);
    np = __fmaf_rn(np, x2, 6.37261928875436e-04f);
    np = __fmaf_rn(np, x2, 4.89352455891786e-03f);
    float num = __fmul_rn(xc, np);
    float dp = 1.19825839466702e-06f;
    dp = __fmaf_rn(dp, x2, 1.18534705686654e-04f);
    dp = __fmaf_rn(dp, x2, 2.26843463243900e-03f);
    dp = __fmaf_rn(dp, x2, 4.89352518554385e-03f);
    float r = __fdiv_rn(num, dp);
    return (ax < 0.0004f) ? x : r;
}

// ---------- double-single helpers ----------
__device__ __forceinline__ void two_sum(float a, float b, float& s, float& e) {
    s = a + b;
    float bb = s - a;
    e = (a - (s - bb)) + (b - bb);
}
__device__ __forceinline__ void two_prod(float a, float b, float& p, float& e) {
    p = a * b;
    e = fmaf(a, b, -p);
}
__device__ __forceinline__ float dif2(float p0, float p1, float q0, float q1) {
    float w = q0 * q1;
    float e = fmaf(q0, q1, -w);
    float r = fmaf(p0, p1, -w);
    return r - e;
}

// ---------- physics: J_uu (bit-exact vs reference) + force (compact) ----------
__device__ __forceinline__ void compute_mf(const float4* __restrict__ y,
                                           const float* sW, const float* sV,
                                           int b, float m[4][4], float force[4])
{
    const float eta[4] = {1.f, -1.f, -1.f, -1.f};
    float4 xv = y[2 * b];
    float4 uv = y[2 * b + 1];
    float x[4] = {xv.x, xv.y, xv.z, xv.w};
    float u[4] = {uv.x, uv.y, uv.z, uv.w};

    float A[4], dk[4];
#pragma unroll
    for (int i = 0; i < 4; i++) {
        float wx = __fmul_rn(sW[i*4+0], x[0]);
        wx = __fmaf_rn(sW[i*4+1], x[1], wx);
        wx = __fmaf_rn(sW[i*4+2], x[2], wx);
        wx = __fmaf_rn(sW[i*4+3], x[3], wx);
        float vx = __fmul_rn(sV[i*4+0], x[0]);
        vx = __fmaf_rn(sV[i*4+1], x[1], vx);
        vx = __fmaf_rn(sV[i*4+2], x[2], vx);
        vx = __fmaf_rn(sV[i*4+3], x[3], vx);
        float t = xla_tanh(wx);
        A[i]  = __fadd_rn(t, vx);
        dk[i] = __fsub_rn(1.0f, __fmul_rn(t, t));
    }

    // ---- J_uu: BIT-CRITICAL layout (matches reference autodiff graph) ----
    float oA[4];
#pragma unroll
    for (int j = 0; j < 4; j++)
        oA[j] = __fmul_rn(0.1f, A[j]);
#pragma unroll
    for (int i = 0; i < 4; i++) {
#pragma unroll
        for (int j = 0; j < 4; j++)
            m[i][j] = __fmul_rn(oA[j], A[i]);
        float xx2 = __fmul_rn(__fmul_rn(0.2f, x[i]), x[i]);
        m[i][i] = __fadd_rn(__fadd_rn(m[i][i], xx2), eta[i]);
    }

    // ---- force: compact algebra (rounding not kappa-amplified) ----
    float G[4][4];
#pragma unroll
    for (int k = 0; k < 4; k++)
#pragma unroll
        for (int j = 0; j < 4; j++)
            G[j][k] = fmaf(sW[k*4+j], dk[k], sV[k*4+j]);

    float s = u[0]*A[0] + u[1]*A[1] + u[2]*A[2] + u[3]*A[3];
    float tbs = 0.1f * s;

    float g[4], ge[4], h[4];
#pragma unroll
    for (int j = 0; j < 4; j++) {
        g[j]  = G[j][0]*u[0] + G[j][1]*u[1] + G[j][2]*u[2] + G[j][3]*u[3];
        ge[j] = G[j][0]*u[0] - G[j][1]*u[1] - G[j][2]*u[2] - G[j][3]*u[3];
        h[j]  = G[0][j]*u[0] + G[1][j]*u[1] + G[2][j]*u[2] + G[3][j]*u[3];
    }
    float p = h[0]*u[0] + h[1]*u[1] + h[2]*u[2] + h[3]*u[3];

#pragma unroll
    for (int j = 0; j < 4; j++) {
        force[j] = -0.2f * x[j] * u[j] * u[j]
                 + 0.5f * ge[j] + tbs * g[j]
                 - 0.5f * eta[j] * h[j] - tbs * h[j]
                 - 0.1f * p * A[j];
    }
}

// ---------- kernel 1: fast path — NO fp64, NO calls ----------
__global__ void __launch_bounds__(256)
rcpl_fast(const float4* __restrict__ y,
          const float* __restrict__ Wg,
          const float* __restrict__ Vg,
          float4* __restrict__ out,
          int B)
{
    __shared__ float sWV[32];
    if (threadIdx.x < 32)
        sWV[threadIdx.x] = (threadIdx.x < 16) ? Wg[threadIdx.x]
                                              : Vg[threadIdx.x - 16];
    __syncthreads();
    const float* sW = sWV;
    const float* sV = sWV + 16;

    int b = blockIdx.x * blockDim.x + threadIdx.x;
    if (b >= B) return;

    float m[4][4], f[4];
    compute_mf(y, sW, sV, b, m, f);

    // compensated 2x2 minors — BIT-CRITICAL
    float s0 = dif2(m[0][0], m[1][1], m[1][0], m[0][1]);
    float s1 = dif2(m[0][0], m[1][2], m[1][0], m[0][2]);
    float s2 = dif2(m[0][0], m[1][3], m[1][0], m[0][3]);
    float s3 = dif2(m[0][1], m[1][2], m[1][1], m[0][2]);
    float s4 = dif2(m[0][1], m[1][3], m[1][1], m[0][3]);
    float s5 = dif2(m[0][2], m[1][3], m[1][2], m[0][3]);

    float c5 = dif2(m[2][2], m[3][3], m[3][2], m[2][3]);
    float c4 = dif2(m[2][1], m[3][3], m[3][1], m[2][3]);
    float c3 = dif2(m[2][1], m[3][2], m[3][1], m[2][2]);
    float c2 = dif2(m[2][0], m[3][3], m[3][0], m[2][3]);
    float c1 = dif2(m[2][0], m[3][2], m[3][0], m[2][2]);
    float c0 = dif2(m[2][0], m[3][1], m[3][0], m[2][1]);

    // determinant in double-single — BIT-CRITICAL
    float hi, lo, p, e, t;
    two_prod(s0, c5, hi, lo);
    two_prod(-s1, c4, p, e); two_sum(hi, p, hi, t); lo += t + e;
    two_prod(s2, c3, p, e);  two_sum(hi, p, hi, t); lo += t + e;
    two_prod(s3, c2, p, e);  two_sum(hi, p, hi, t); lo += t + e;
    two_prod(-s4, c1, p, e); two_sum(hi, p, hi, t); lo += t + e;
    two_prod(s5, c0, p, e);  two_sum(hi, p, hi, t); lo += t + e;

    float adj[4][4];
    adj[0][0] =  m[1][1]*c5 - m[1][2]*c4 + m[1][3]*c3;
    adj[0][1] = -m[0][1]*c5 + m[0][2]*c4 - m[0][3]*c3;
    adj[0][2] =  m[3][1]*s5 - m[3][2]*s4 + m[3][3]*s3;
    adj[0][3] = -m[2][1]*s5 + m[2][2]*s4 - m[2][3]*s3;
    adj[1][0] = -m[1][0]*c5 + m[1][2]*c2 - m[1][3]*c1;
    adj[1][1] =  m[0][0]*c5 - m[0][2]*c2 + m[0][3]*c1;
    adj[1][2] = -m[3][0]*s5 + m[3][2]*s2 - m[3][3]*s1;
    adj[1][3] =  m[2][0]*s5 - m[2][2]*s2 + m[2][3]*s1;
    adj[2][0] =  m[1][0]*c4 - m[1][1]*c2 + m[1][3]*c0;
    adj[2][1] = -m[0][0]*c4 + m[0][1]*c2 - m[0][3]*c0;
    adj[2][2] =  m[3][0]*s4 - m[3][1]*s2 + m[3][3]*s0;
    adj[2][3] = -m[2][0]*s4 + m[2][1]*s2 - m[2][3]*s0;
    adj[3][0] = -m[1][0]*c3 + m[1][1]*c1 - m[1][2]*c0;
    adj[3][1] =  m[0][0]*c3 - m[0][1]*c1 + m[0][2]*c0;
    adj[3][2] = -m[3][0]*s3 + m[3][1]*s1 - m[3][2]*s0;
    adj[3][3] =  m[2][0]*s3 - m[2][1]*s1 + m[2][2]*s0;

    // route iff det^2 < (4*RCOND)^2 * ||m||_F^2 * ||adj||_F^2
    float sF2 = 0.f, sAdj2 = 0.f;
#pragma unroll
    for (int i = 0; i < 4; i++)
#pragma unroll
        for (int j = 0; j < 4; j++) {
            sF2   = fmaf(m[i][j],   m[i][j],   sF2);
            sAdj2 = fmaf(adj[i][j], adj[i][j], sAdj2);
        }
    float det1 = hi + lo;
    const float CR = 4.0f * RCOND;
    if (det1 * det1 < (CR * CR) * sF2 * sAdj2) {
        unsigned idx = atomicAdd(&g_slow_count, 1u);
        if (idx < MAX_SLOW) g_slow_idx[idx] = b;
    }

    float inv = 1.0f / hi;
    inv = fmaf(-lo, inv * inv, inv);   // 1/(hi+lo)

    float4 res;
    res.x = (f[0]*adj[0][0] + f[1]*adj[1][0] + f[2]*adj[2][0] + f[3]*adj[3][0]) * inv;
    res.y = (f[0]*adj[0][1] + f[1]*adj[1][1] + f[2]*adj[2][1] + f[3]*adj[3][1]) * inv;
    res.z = (f[0]*adj[0][2] + f[1]*adj[1][2] + f[2]*adj[2][2] + f[3]*adj[3][2]) * inv;
    res.w = (f[0]*adj[0][3] + f[1]*adj[1][3] + f[2]*adj[2][3] + f[3]*adj[3][3]) * inv;
    out[b] = res;
}

// ---------- kernel 2: slow path — fp64 deflation pinv + counter reset ------
__global__ void rcpl_slow(const float4* __restrict__ y,
                          const float* __restrict__ Wg,
                          const float* __restrict__ Vg,
                          float4* __restrict__ out)
{
    __shared__ float sWV[32];
    if (threadIdx.x < 32)
        sWV[threadIdx.x] = (threadIdx.x < 16) ? Wg[threadIdx.x]
                                              : Vg[threadIdx.x - 16];
    __syncthreads();
    const float* sW = sWV;
    const float* sV = sWV + 16;

    unsigned count = g_slow_count;
    if (count > MAX_SLOW) count = MAX_SLOW;

    for (unsigned i = blockIdx.x * blockDim.x + threadIdx.x; i < count;
         i += gridDim.x * blockDim.x)
    {
        int b = g_slow_idx[i];
        float mm[4][4], ff[4];
        compute_mf(y, sW, sV, b, mm, ff);

        double M[4][4], F[4];
#pragma unroll
        for (int r = 0; r < 4; r++) {
            F[r] = (double)ff[r];
#pragma unroll
            for (int c = 0; c < 4; c++)
                M[r][c] = (double)mm[r][c];
        }

        double s0 = M[0][0]*M[1][1] - M[1][0]*M[0][1];
        double s1 = M[0][0]*M[1][2] - M[1][0]*M[0][2];
        double s2 = M[0][0]*M[1][3] - M[1][0]*M[0][3];
        double s3 = M[0][1]*M[1][2] - M[1][1]*M[0][2];
        double s4 = M[0][1]*M[1][3] - M[1][1]*M[0][3];
        double s5 = M[0][2]*M[1][3] - M[1][2]*M[0][3];
        double c5 = M[2][2]*M[3][3] - M[3][2]*M[2][3];
        double c4 = M[2][1]*M[3][3] - M[3][1]*M[2][3];
        double c3 = M[2][1]*M[3][2] - M[3][1]*M[2][2];
        double c2 = M[2][0]*M[3][3] - M[3][0]*M[2][3];
        double c1 = M[2][0]*M[3][2] - M[3][0]*M[2][2];
        double c0 = M[2][0]*M[3][1] - M[3][0]*M[2][1];

        double det = s0*c5 - s1*c4 + s2*c3 + s3*c2 - s4*c1 + s5*c0;

        double adj[4][4];
        adj[0][0] =  M[1][1]*c5 - M[1][2]*c4 + M[1][3]*c3;
        adj[0][1] = -M[0][1]*c5 + M[0][2]*c4 - M[0][3]*c3;
        adj[0][2] =  M[3][1]*s5 - M[3][2]*s4 + M[3][3]*s3;
        adj[0][3] = -M[2][1]*s5 + M[2][2]*s4 - M[2][3]*s3;
        adj[1][0] = -M[1][0]*c5 + M[1][2]*c2 - M[1][3]*c1;
        adj[1][1] =  M[0][0]*c5 - M[0][2]*c2 + M[0][3]*c1;
        adj[1][2] = -M[3][0]*s5 + M[3][2]*s2 - M[3][3]*s1;
        adj[1][3] =  M[2][0]*s5 - M[2][2]*s2 + M[2][3]*s1;
        adj[2][0] =  M[1][0]*c4 - M[1][1]*c2 + M[1][3]*c0;
        adj[2][1] = -M[0][0]*c4 + M[0][1]*c2 - M[0][3]*c0;
        adj[2][2] =  M[3][0]*s4 - M[3][1]*s2 + M[3][3]*s0;
        adj[2][3] = -M[2][0]*s4 + M[2][1]*s2 - M[2][3]*s0;
        adj[3][0] = -M[1][0]*c3 + M[1][1]*c1 - M[1][2]*c0;
        adj[3][1] =  M[0][0]*c3 - M[0][1]*c1 + M[0][2]*c0;
        adj[3][2] = -M[3][0]*s3 + M[3][1]*s1 - M[3][2]*s0;
        adj[3][3] =  M[2][0]*s3 - M[2][1]*s1 + M[2][2]*s0;

        double rdet = (double)__frcp_rn((float)det);
        rdet = rdet * (2.0 - det * rdet);
        rdet = rdet * (2.0 - det * rdet);

        double acc[4];
#pragma unroll
        for (int j = 0; j < 4; j++)
            acc[j] = (F[0]*adj[0][j] + F[1]*adj[1][j]
                    + F[2]*adj[2][j] + F[3]*adj[3][j]) * rdet;

        // null direction: dominant adjugate column + one refinement multiply
        double cn[4];
#pragma unroll
        for (int c = 0; c < 4; c++)
            cn[c] = adj[0][c]*adj[0][c] + adj[1][c]*adj[1][c]
                  + adj[2][c]*adj[2][c] + adj[3][c]*adj[3][c];
        int cbest = 0;
        if (cn[1] > cn[cbest]) cbest = 1;
        if (cn[2] > cn[cbest]) cbest = 2;
        if (cn[3] > cn[cbest]) cbest = 3;
        double v[4] = {adj[0][cbest], adj[1][cbest], adj[2][cbest], adj[3][cbest]};
        double v2[4];
#pragma unroll
        for (int r = 0; r < 4; r++)
            v2[r] = adj[r][0]*v[0] + adj[r][1]*v[1] + adj[r][2]*v[2] + adj[r][3]*v[3];

        double Mv[4];
#pragma unroll
        for (int r = 0; r < 4; r++)
            Mv[r] = M[r][0]*v2[0] + M[r][1]*v2[1] + M[r][2]*v2[2] + M[r][3]*v2[3];
        double num = v2[0]*Mv[0] + v2[1]*Mv[1] + v2[2]*Mv[2] + v2[3]*Mv[3];
        double den = v2[0]*v2[0] + v2[1]*v2[1] + v2[2]*v2[2] + v2[3]*v2[3];

        // sigma_max^2 via power iteration on M^2 (compare in squares)
        double tn[4];
#pragma unroll
        for (int c = 0; c < 4; c++)
            tn[c] = M[0][c]*M[0][c] + M[1][c]*M[1][c]
                  + M[2][c]*M[2][c] + M[3][c]*M[3][c];
        int tbest = 0;
        if (tn[1] > tn[tbest]) tbest = 1;
        if (tn[2] > tn[tbest]) tbest = 2;
        if (tn[3] > tn[tbest]) tbest = 3;
        double t[4] = {M[0][tbest], M[1][tbest], M[2][tbest], M[3][tbest]};
#pragma unroll
        for (int it = 0; it < 6; it++) {
            double t0 = M[0][0]*t[0] + M[0][1]*t[1] + M[0][2]*t[2] + M[0][3]*t[3];
            double t1 = M[1][0]*t[0] + M[1][1]*t[1] + M[1][2]*t[2] + M[1][3]*t[3];
            double t2 = M[2][0]*t[0] + M[2][1]*t[1] + M[2][2]*t[2] + M[2][3]*t[3];
            double t3 = M[3][0]*t[0] + M[3][1]*t[1] + M[3][2]*t[2] + M[3][3]*t[3];
            t[0] = t0; t[1] = t1; t[2] = t2; t[3] = t3;
        }
        double z0 = M[0][0]*t[0] + M[0][1]*t[1] + M[0][2]*t[2] + M[0][3]*t[3];
        double z1 = M[1][0]*t[0] + M[1][1]*t[1] + M[1][2]*t[2] + M[1][3]*t[3];
        double z2 = M[2][0]*t[0] + M[2][1]*t[1] + M[2][2]*t[2] + M[2][3]*t[3];
        double z3 = M[3][0]*t[0] + M[3][1]*t[1] + M[3][2]*t[2] + M[3][3]*t[3];
        double zz = z0*z0 + z1*z1 + z2*z2 + z3*z3;
        double tt = t[0]*t[0] + t[1]*t[1] + t[2]*t[2] + t[3]*t[3];
        double R2 = (double)RCOND * (double)RCOND;
        bool keep = (num*num)*tt > R2*zz*(den*den);

        if (!keep) {
            double rden = (double)__frcp_rn((float)den);
            rden = rden * (2.0 - den * rden);
            rden = rden * (2.0 - den * rden);
            double proj = (v2[0]*acc[0] + v2[1]*acc[1]
                         + v2[2]*acc[2] + v2[3]*acc[3]) * rden;
#pragma unroll
            for (int j = 0; j < 4; j++)
                acc[j] -= proj * v2[j];
        }

        out[b] = make_float4((float)acc[0], (float)acc[1],
                             (float)acc[2], (float)acc[3]);
    }

    // last-finishing block resets counters for the next graph replay
    __syncthreads();
    if (threadIdx.x == 0) {
        unsigned d = atomicAdd(&g_done_blocks, 1u);
        if (d == gridDim.x - 1u) {
            g_slow_count = 0u;
            g_done_blocks = 0u;
        }
    }
}

extern "C" void kernel_launch(void* const* d_in, const int* in_sizes, int n_in,
                              void* d_out, int out_size)
{
    const float* y = (const float*)d_in[0];
    const float* W = (const float*)d_in[1];
    const float* V = (const float*)d_in[2];
    int B = in_sizes[0] / 8;   // y is [B, 8]

    int threads = 256;
    int blocks = (B + threads - 1) / threads;
    rcpl_fast<<<blocks, threads>>>((const float4*)y, W, V, (float4*)d_out, B);
    rcpl_slow<<<64, 128>>>((const float4*)y, W, V, (float4*)d_out);
}

// round 17
// speedup vs baseline: 1.4776x; 1.4776x over previous
#include <cuda_runtime.h>

// Relativistic charged-particle Lagrangian dynamics — TWO kernels.
// R17 = R16 fast kernel (bit-identical, ~4.5us: no fp64/no calls, low regs)
// + slow kernel rewritten in double-single f32 (FFMA pipe) instead of fp64.
// B300 fp64 costs ~64cyc/op for a lone warp -> R16's slow kernel was an
// 18us serial straggler; ds-f32 cuts the same math to ~3-4us. Precision:
// ds (~1e-13) for minors/det/adjugate/solve/null-dir/num/projection; plain
// f32 for sigma_max power iteration + norms (decision flips need |lam/sig -
// RCOND| < 1e-6 relative: probability ~7e-6). pinv semantics unchanged.

#define RCOND 4.7683716e-6f   /* 10 * 4 * eps(f32): jnp pinv default */
#define MAX_SLOW 262144

__device__ unsigned int g_slow_count = 0u;
__device__ unsigned int g_done_blocks = 0u;
__device__ int g_slow_idx[MAX_SLOW];

// ---------- XLA GPU f32 tanh ----------
__device__ __forceinline__ float xla_tanh(float x) {
    float ax = fabsf(x);
    float xc = fminf(fmaxf(x, -7.90531110763549805f), 7.90531110763549805f);
    float x2 = __fmul_rn(xc, xc);
    float np = -2.76076847742355e-16f;
    np = __fmaf_rn(np, x2, 2.00018790482477e-13f);
    np = __fmaf_rn(np, x2, -8.60467152213735e-11f);
    np = __fmaf_rn(np, x2, 5.12229709037114e-08f);
    np = __fmaf_rn(np, x2, 1.48572235717979e-05f);
    np = __fmaf_rn(np, x2, 6.37261928875436e-04f);
    np = __fmaf_rn(np, x2, 4.89352455891786e-03f);
    float num = __fmul_rn(xc, np);
    float dp = 1.19825839466702e-06f;
    dp = __fmaf_rn(dp, x2, 1.18534705686654e-04f);
    dp = __fmaf_rn(dp, x2, 2.26843463243900e-03f);
    dp = __fmaf_rn(dp, x2, 4.89352518554385e-03f);
    float r = __fdiv_rn(num, dp);
    return (ax < 0.0004f) ? x : r;
}

// ---------- error-free transforms ----------
__device__ __forceinline__ void two_sum(float a, float b, float& s, float& e) {
    s = a + b;
    float bb = s - a;
    e = (a - (s - bb)) + (b - bb);
}
__device__ __forceinline__ void two_prod(float a, float b, float& p, float& e) {
    p = a * b;
    e = fmaf(a, b, -p);
}
__device__ __forceinline__ float dif2(float p0, float p1, float q0, float q1) {
    float w = q0 * q1;
    float e = fmaf(q0, q1, -w);
    float r = fmaf(p0, p1, -w);
    return r - e;
}

// ---------- double-single (float-float) arithmetic ----------
struct ds2 { float h, l; };
__device__ __forceinline__ ds2 ds_mk(float h, float l) { ds2 r; r.h = h; r.l = l; return r; }
__device__ __forceinline__ ds2 ds_norm(float s, float e) {
    float h = s + e;
    float l = e - (h - s);
    return ds_mk(h, l);
}
__device__ __forceinline__ ds2 ds_add(ds2 a, ds2 b) {
    float s, e;
    two_sum(a.h, b.h, s, e);
    e += a.l + b.l;
    return ds_norm(s, e);
}
__device__ __forceinline__ ds2 ds_sub(ds2 a, ds2 b) { return ds_add(a, ds_mk(-b.h, -b.l)); }
__device__ __forceinline__ ds2 ds_mul(ds2 a, ds2 b) {
    float p, e;
    two_prod(a.h, b.h, p, e);
    e = fmaf(a.h, b.l, fmaf(a.l, b.h, e));
    return ds_norm(p, e);
}
__device__ __forceinline__ ds2 ds_mulf(ds2 a, float b) {
    float p, e;
    two_prod(a.h, b, p, e);
    e = fmaf(a.l, b, e);
    return ds_norm(p, e);
}
__device__ __forceinline__ ds2 ds_pff(float a, float b) {  // exact a*b
    float p, e;
    two_prod(a, b, p, e);
    return ds_mk(p, e);
}
__device__ __forceinline__ ds2 ds_recip(ds2 d) {
    ds2 r = ds_mk(__frcp_rn(d.h), 0.f);
#pragma unroll
    for (int it = 0; it < 2; it++) {
        ds2 e = ds_sub(ds_mk(1.f, 0.f), ds_mul(d, r));
        r = ds_add(r, ds_mul(r, e));
    }
    return r;
}
__device__ __forceinline__ float ds_f(ds2 a) { return a.h + a.l; }

// ---------- physics: J_uu (bit-exact vs reference) + force (compact) ----------
__device__ __forceinline__ void compute_mf(const float4* __restrict__ y,
                                           const float* sW, const float* sV,
                                           int b, float m[4][4], float force[4])
{
    const float eta[4] = {1.f, -1.f, -1.f, -1.f};
    float4 xv = y[2 * b];
    float4 uv = y[2 * b + 1];
    float x[4] = {xv.x, xv.y, xv.z, xv.w};
    float u[4] = {uv.x, uv.y, uv.z, uv.w};

    float A[4], dk[4];
#pragma unroll
    for (int i = 0; i < 4; i++) {
        float wx = __fmul_rn(sW[i*4+0], x[0]);
        wx = __fmaf_rn(sW[i*4+1], x[1], wx);
        wx = __fmaf_rn(sW[i*4+2], x[2], wx);
        wx = __fmaf_rn(sW[i*4+3], x[3], wx);
        float vx = __fmul_rn(sV[i*4+0], x[0]);
        vx = __fmaf_rn(sV[i*4+1], x[1], vx);
        vx = __fmaf_rn(sV[i*4+2], x[2], vx);
        vx = __fmaf_rn(sV[i*4+3], x[3], vx);
        float t = xla_tanh(wx);
        A[i]  = __fadd_rn(t, vx);
        dk[i] = __fsub_rn(1.0f, __fmul_rn(t, t));
    }

    // ---- J_uu: BIT-CRITICAL layout ----
    float oA[4];
#pragma unroll
    for (int j = 0; j < 4; j++)
        oA[j] = __fmul_rn(0.1f, A[j]);
#pragma unroll
    for (int i = 0; i < 4; i++) {
#pragma unroll
        for (int j = 0; j < 4; j++)
            m[i][j] = __fmul_rn(oA[j], A[i]);
        float xx2 = __fmul_rn(__fmul_rn(0.2f, x[i]), x[i]);
        m[i][i] = __fadd_rn(__fadd_rn(m[i][i], xx2), eta[i]);
    }

    // ---- force (un-amplified) ----
    float G[4][4];
#pragma unroll
    for (int k = 0; k < 4; k++)
#pragma unroll
        for (int j = 0; j < 4; j++)
            G[j][k] = fmaf(sW[k*4+j], dk[k], sV[k*4+j]);

    float s = u[0]*A[0] + u[1]*A[1] + u[2]*A[2] + u[3]*A[3];
    float tbs = 0.1f * s;

    float g[4], ge[4], h[4];
#pragma unroll
    for (int j = 0; j < 4; j++) {
        g[j]  = G[j][0]*u[0] + G[j][1]*u[1] + G[j][2]*u[2] + G[j][3]*u[3];
        ge[j] = G[j][0]*u[0] - G[j][1]*u[1] - G[j][2]*u[2] - G[j][3]*u[3];
        h[j]  = G[0][j]*u[0] + G[1][j]*u[1] + G[2][j]*u[2] + G[3][j]*u[3];
    }
    float p = h[0]*u[0] + h[1]*u[1] + h[2]*u[2] + h[3]*u[3];

#pragma unroll
    for (int j = 0; j < 4; j++) {
        force[j] = -0.2f * x[j] * u[j] * u[j]
                 + 0.5f * ge[j] + tbs * g[j]
                 - 0.5f * eta[j] * h[j] - tbs * h[j]
                 - 0.1f * p * A[j];
    }
}

// ---------- kernel 1: fast path — NO fp64, NO calls (R16, passing bits) ----
__global__ void __launch_bounds__(256)
rcpl_fast(const float4* __restrict__ y,
          const float* __restrict__ Wg,
          const float* __restrict__ Vg,
          float4* __restrict__ out,
          int B)
{
    __shared__ float sWV[32];
    if (threadIdx.x < 32)
        sWV[threadIdx.x] = (threadIdx.x < 16) ? Wg[threadIdx.x]
                                              : Vg[threadIdx.x - 16];
    __syncthreads();
    const float* sW = sWV;
    const float* sV = sWV + 16;

    int b = blockIdx.x * blockDim.x + threadIdx.x;
    if (b >= B) return;

    float m[4][4], f[4];
    compute_mf(y, sW, sV, b, m, f);

    float s0 = dif2(m[0][0], m[1][1], m[1][0], m[0][1]);
    float s1 = dif2(m[0][0], m[1][2], m[1][0], m[0][2]);
    float s2 = dif2(m[0][0], m[1][3], m[1][0], m[0][3]);
    float s3 = dif2(m[0][1], m[1][2], m[1][1], m[0][2]);
    float s4 = dif2(m[0][1], m[1][3], m[1][1], m[0][3]);
    float s5 = dif2(m[0][2], m[1][3], m[1][2], m[0][3]);

    float c5 = dif2(m[2][2], m[3][3], m[3][2], m[2][3]);
    float c4 = dif2(m[2][1], m[3][3], m[3][1], m[2][3]);
    float c3 = dif2(m[2][1], m[3][2], m[3][1], m[2][2]);
    float c2 = dif2(m[2][0], m[3][3], m[3][0], m[2][3]);
    float c1 = dif2(m[2][0], m[3][2], m[3][0], m[2][2]);
    float c0 = dif2(m[2][0], m[3][1], m[3][0], m[2][1]);

    float hi, lo, p, e, t;
    two_prod(s0, c5, hi, lo);
    two_prod(-s1, c4, p, e); two_sum(hi, p, hi, t); lo += t + e;
    two_prod(s2, c3, p, e);  two_sum(hi, p, hi, t); lo += t + e;
    two_prod(s3, c2, p, e);  two_sum(hi, p, hi, t); lo += t + e;
    two_prod(-s4, c1, p, e); two_sum(hi, p, hi, t); lo += t + e;
    two_prod(s5, c0, p, e);  two_sum(hi, p, hi, t); lo += t + e;

    float adj[4][4];
    adj[0][0] =  m[1][1]*c5 - m[1][2]*c4 + m[1][3]*c3;
    adj[0][1] = -m[0][1]*c5 + m[0][2]*c4 - m[0][3]*c3;
    adj[0][2] =  m[3][1]*s5 - m[3][2]*s4 + m[3][3]*s3;
    adj[0][3] = -m[2][1]*s5 + m[2][2]*s4 - m[2][3]*s3;
    adj[1][0] = -m[1][0]*c5 + m[1][2]*c2 - m[1][3]*c1;
    adj[1][1] =  m[0][0]*c5 - m[0][2]*c2 + m[0][3]*c1;
    adj[1][2] = -m[3][0]*s5 + m[3][2]*s2 - m[3][3]*s1;
    adj[1][3] =  m[2][0]*s5 - m[2][2]*s2 + m[2][3]*s1;
    adj[2][0] =  m[1][0]*c4 - m[1][1]*c2 + m[1][3]*c0;
    adj[2][1] = -m[0][0]*c4 + m[0][1]*c2 - m[0][3]*c0;
    adj[2][2] =  m[3][0]*s4 - m[3][1]*s2 + m[3][3]*s0;
    adj[2][3] = -m[2][0]*s4 + m[2][1]*s2 - m[2][3]*s0;
    adj[3][0] = -m[1][0]*c3 + m[1][1]*c1 - m[1][2]*c0;
    adj[3][1] =  m[0][0]*c3 - m[0][1]*c1 + m[0][2]*c0;
    adj[3][2] = -m[3][0]*s3 + m[3][1]*s1 - m[3][2]*s0;
    adj[3][3] =  m[2][0]*s3 - m[2][1]*s1 + m[2][2]*s0;

    float sF2 = 0.f, sAdj2 = 0.f;
#pragma unroll
    for (int i = 0; i < 4; i++)
#pragma unroll
        for (int j = 0; j < 4; j++) {
            sF2   = fmaf(m[i][j],   m[i][j],   sF2);
            sAdj2 = fmaf(adj[i][j], adj[i][j], sAdj2);
        }
    float det1 = hi + lo;
    const float CR = 4.0f * RCOND;
    if (det1 * det1 < (CR * CR) * sF2 * sAdj2) {
        unsigned idx = atomicAdd(&g_slow_count, 1u);
        if (idx < MAX_SLOW) g_slow_idx[idx] = b;
    }

    float inv = 1.0f / hi;
    inv = fmaf(-lo, inv * inv, inv);   // 1/(hi+lo)

    float4 res;
    res.x = (f[0]*adj[0][0] + f[1]*adj[1][0] + f[2]*adj[2][0] + f[3]*adj[3][0]) * inv;
    res.y = (f[0]*adj[0][1] + f[1]*adj[1][1] + f[2]*adj[2][1] + f[3]*adj[3][1]) * inv;
    res.z = (f[0]*adj[0][2] + f[1]*adj[1][2] + f[2]*adj[2][2] + f[3]*adj[3][2]) * inv;
    res.w = (f[0]*adj[0][3] + f[1]*adj[1][3] + f[2]*adj[2][3] + f[3]*adj[3][3]) * inv;
    out[b] = res;
}

// ---------- kernel 2: slow path — double-single pinv + counter reset -------
__global__ void rcpl_slow(const float4* __restrict__ y,
                          const float* __restrict__ Wg,
                          const float* __restrict__ Vg,
                          float4* __restrict__ out)
{
    __shared__ float sWV[32];
    if (threadIdx.x < 32)
        sWV[threadIdx.x] = (threadIdx.x < 16) ? Wg[threadIdx.x]
                                              : Vg[threadIdx.x - 16];
    __syncthreads();
    const float* sW = sWV;
    const float* sV = sWV + 16;

    unsigned count = g_slow_count;
    if (count > MAX_SLOW) count = MAX_SLOW;

    for (unsigned i = blockIdx.x * blockDim.x + threadIdx.x; i < count;
         i += gridDim.x * blockDim.x)
    {
        int b = g_slow_idx[i];
        float mm[4][4], ff[4];
        compute_mf(y, sW, sV, b, mm, ff);

        // ---- minors + det in ds (exact 2x2s, ~1e-13 det) ----
        ds2 S0 = ds_sub(ds_pff(mm[0][0], mm[1][1]), ds_pff(mm[1][0], mm[0][1]));
        ds2 S1 = ds_sub(ds_pff(mm[0][0], mm[1][2]), ds_pff(mm[1][0], mm[0][2]));
        ds2 S2 = ds_sub(ds_pff(mm[0][0], mm[1][3]), ds_pff(mm[1][0], mm[0][3]));
        ds2 S3 = ds_sub(ds_pff(mm[0][1], mm[1][2]), ds_pff(mm[1][1], mm[0][2]));
        ds2 S4 = ds_sub(ds_pff(mm[0][1], mm[1][3]), ds_pff(mm[1][1], mm[0][3]));
        ds2 S5 = ds_sub(ds_pff(mm[0][2], mm[1][3]), ds_pff(mm[1][2], mm[0][3]));
        ds2 C5 = ds_sub(ds_pff(mm[2][2], mm[3][3]), ds_pff(mm[3][2], mm[2][3]));
        ds2 C4 = ds_sub(ds_pff(mm[2][1], mm[3][3]), ds_pff(mm[3][1], mm[2][3]));
        ds2 C3 = ds_sub(ds_pff(mm[2][1], mm[3][2]), ds_pff(mm[3][1], mm[2][2]));
        ds2 C2 = ds_sub(ds_pff(mm[2][0], mm[3][3]), ds_pff(mm[3][0], mm[2][3]));
        ds2 C1 = ds_sub(ds_pff(mm[2][0], mm[3][2]), ds_pff(mm[3][0], mm[2][2]));
        ds2 C0 = ds_sub(ds_pff(mm[2][0], mm[3][1]), ds_pff(mm[3][0], mm[2][1]));

        ds2 det = ds_mul(S0, C5);
        det = ds_sub(det, ds_mul(S1, C4));
        det = ds_add(det, ds_mul(S2, C3));
        det = ds_add(det, ds_mul(S3, C2));
        det = ds_sub(det, ds_mul(S4, C1));
        det = ds_add(det, ds_mul(S5, C0));

        // ---- adjugate in ds ----
        ds2 adj[4][4];
        adj[0][0] = ds_add(ds_sub(ds_mulf(C5, mm[1][1]), ds_mulf(C4, mm[1][2])), ds_mulf(C3, mm[1][3]));
        adj[0][1] = ds_sub(ds_sub(ds_mulf(C4, mm[0][2]), ds_mulf(C5, mm[0][1])), ds_mulf(C3, mm[0][3]));
        adj[0][2] = ds_add(ds_sub(ds_mulf(S5, mm[3][1]), ds_mulf(S4, mm[3][2])), ds_mulf(S3, mm[3][3]));
        adj[0][3] = ds_sub(ds_sub(ds_mulf(S4, mm[2][2]), ds_mulf(S5, mm[2][1])), ds_mulf(S3, mm[2][3]));
        adj[1][0] = ds_sub(ds_sub(ds_mulf(C2, mm[1][2]), ds_mulf(C5, mm[1][0])), ds_mulf(C1, mm[1][3]));
        adj[1][1] = ds_add(ds_sub(ds_mulf(C5, mm[0][0]), ds_mulf(C2, mm[0][2])), ds_mulf(C1, mm[0][3]));
        adj[1][2] = ds_sub(ds_sub(ds_mulf(S2, mm[3][2]), ds_mulf(S5, mm[3][0])), ds_mulf(S1, mm[3][3]));
        adj[1][3] = ds_add(ds_sub(ds_mulf(S5, mm[2][0]), ds_mulf(S2, mm[2][2])), ds_mulf(S1, mm[2][3]));
        adj[2][0] = ds_add(ds_sub(ds_mulf(C4, mm[1][0]), ds_mulf(C2, mm[1][1])), ds_mulf(C0, mm[1][3]));
        adj[2][1] = ds_sub(ds_sub(ds_mulf(C2, mm[0][1]), ds_mulf(C4, mm[0][0])), ds_mulf(C0, mm[0][3]));
        adj[2][2] = ds_add(ds_sub(ds_mulf(S4, mm[3][0]), ds_mulf(S2, mm[3][1])), ds_mulf(S0, mm[3][3]));
        adj[2][3] = ds_sub(ds_sub(ds_mulf(S2, mm[2][1]), ds_mulf(S4, mm[2][0])), ds_mulf(S0, mm[2][3]));
        adj[3][0] = ds_sub(ds_sub(ds_mulf(C1, mm[1][1]), ds_mulf(C3, mm[1][0])), ds_mulf(C0, mm[1][2]));
        adj[3][1] = ds_add(ds_sub(ds_mulf(C3, mm[0][0]), ds_mulf(C1, mm[0][1])), ds_mulf(C0, mm[0][2]));
        adj[3][2] = ds_sub(ds_sub(ds_mulf(S1, mm[3][1]), ds_mulf(S3, mm[3][0])), ds_mulf(S0, mm[3][2]));
        adj[3][3] = ds_add(ds_sub(ds_mulf(S3, mm[2][0]), ds_mulf(S1, mm[2][1])), ds_mulf(S0, mm[2][2]));

        // ---- acc = adj^T f / det (ds) ----
        ds2 rdet = ds_recip(det);
        ds2 acc[4];
#pragma unroll
        for (int j = 0; j < 4; j++) {
            ds2 a = ds_mulf(adj[0][j], ff[0]);
            a = ds_add(a, ds_mulf(adj[1][j], ff[1]));
            a = ds_add(a, ds_mulf(adj[2][j], ff[2]));
            a = ds_add(a, ds_mulf(adj[3][j], ff[3]));
            acc[j] = ds_mul(a, rdet);
        }

        // ---- null direction: dominant adjugate column (f32 selection) ----
        float cn[4];
#pragma unroll
        for (int c = 0; c < 4; c++)
            cn[c] = adj[0][c].h*adj[0][c].h + adj[1][c].h*adj[1][c].h
                  + adj[2][c].h*adj[2][c].h + adj[3][c].h*adj[3][c].h;
        int cbest = 0;
        if (cn[1] > cn[cbest]) cbest = 1;
        if (cn[2] > cn[cbest]) cbest = 2;
        if (cn[3] > cn[cbest]) cbest = 3;
        ds2 v[4] = {adj[0][cbest], adj[1][cbest], adj[2][cbest], adj[3][cbest]};
        // refinement multiply: v2 = adj * v  (ds)
        ds2 v2[4];
#pragma unroll
        for (int r = 0; r < 4; r++) {
            ds2 a = ds_mul(adj[r][0], v[0]);
            a = ds_add(a, ds_mul(adj[r][1], v[1]));
            a = ds_add(a, ds_mul(adj[r][2], v[2]));
            a = ds_add(a, ds_mul(adj[r][3], v[3]));
            v2[r] = a;
        }

        // ---- Rayleigh lam_min: num = v2^T M v2 (ds; cancellation-critical) --
        ds2 Mv[4];
#pragma unroll
        for (int r = 0; r < 4; r++) {
            ds2 a = ds_mulf(v2[0], mm[r][0]);
            a = ds_add(a, ds_mulf(v2[1], mm[r][1]));
            a = ds_add(a, ds_mulf(v2[2], mm[r][2]));
            a = ds_add(a, ds_mulf(v2[3], mm[r][3]));
            Mv[r] = a;
        }
        ds2 numd = ds_mul(v2[0], Mv[0]);
        numd = ds_add(numd, ds_mul(v2[1], Mv[1]));
        numd = ds_add(numd, ds_mul(v2[2], Mv[2]));
        numd = ds_add(numd, ds_mul(v2[3], Mv[3]));
        float num = ds_f(numd);

        ds2 dend = ds_mul(v2[0], v2[0]);
        dend = ds_add(dend, ds_mul(v2[1], v2[1]));
        dend = ds_add(dend, ds_mul(v2[2], v2[2]));
        dend = ds_add(dend, ds_mul(v2[3], v2[3]));
        float den = ds_f(dend);

        // ---- sigma_max^2 via f32 power iteration (decision tolerance 1e-6) --
        float tn[4];
#pragma unroll
        for (int c = 0; c < 4; c++)
            tn[c] = mm[0][c]*mm[0][c] + mm[1][c]*mm[1][c]
                  + mm[2][c]*mm[2][c] + mm[3][c]*mm[3][c];
        int tbest = 0;
        if (tn[1] > tn[tbest]) tbest = 1;
        if (tn[2] > tn[tbest]) tbest = 2;
        if (tn[3] > tn[tbest]) tbest = 3;
        float t[4] = {mm[0][tbest], mm[1][tbest], mm[2][tbest], mm[3][tbest]};
#pragma unroll
        for (int it = 0; it < 6; it++) {
            float t0 = mm[0][0]*t[0] + mm[0][1]*t[1] + mm[0][2]*t[2] + mm[0][3]*t[3];
            float t1 = mm[1][0]*t[0] + mm[1][1]*t[1] + mm[1][2]*t[2] + mm[1][3]*t[3];
            float t2 = mm[2][0]*t[0] + mm[2][1]*t[1] + mm[2][2]*t[2] + mm[2][3]*t[3];
            float t3 = mm[3][0]*t[0] + mm[3][1]*t[1] + mm[3][2]*t[2] + mm[3][3]*t[3];
            // renormalize to avoid overflow/underflow across iterations
            float nrm = fabsf(t0) + fabsf(t1) + fabsf(t2) + fabsf(t3);
            float rs = __frcp_rn(nrm);
            t[0] = t0 * rs; t[1] = t1 * rs; t[2] = t2 * rs; t[3] = t3 * rs;
        }
        float z0 = mm[0][0]*t[0] + mm[0][1]*t[1] + mm[0][2]*t[2] + mm[0][3]*t[3];
        float z1 = mm[1][0]*t[0] + mm[1][1]*t[1] + mm[1][2]*t[2] + mm[1][3]*t[3];
        float z2 = mm[2][0]*t[0] + mm[2][1]*t[1] + mm[2][2]*t[2] + mm[2][3]*t[3];
        float z3 = mm[3][0]*t[0] + mm[3][1]*t[1] + mm[3][2]*t[2] + mm[3][3]*t[3];
        float zz = z0*z0 + z1*z1 + z2*z2 + z3*z3;
        float tt = t[0]*t[0] + t[1]*t[1] + t[2]*t[2] + t[3]*t[3];

        // keep iff (num/den)^2 > RCOND^2 * zz/tt  <=>  num^2*tt > R2*zz*den^2
        float R2 = RCOND * RCOND;
        bool keep = (num * num) * tt > R2 * zz * (den * den);

        if (!keep) {
            ds2 rden = ds_recip(dend);
            ds2 pr = ds_mul(v2[0], acc[0]);
            pr = ds_add(pr, ds_mul(v2[1], acc[1]));
            pr = ds_add(pr, ds_mul(v2[2], acc[2]));
            pr = ds_add(pr, ds_mul(v2[3], acc[3]));
            pr = ds_mul(pr, rden);
#pragma unroll
            for (int j = 0; j < 4; j++)
                acc[j] = ds_sub(acc[j], ds_mul(pr, v2[j]));
        }

        out[b] = make_float4(ds_f(acc[0]), ds_f(acc[1]),
                             ds_f(acc[2]), ds_f(acc[3]));
    }

    // last-finishing block resets counters for the next graph replay
    __syncthreads();
    if (threadIdx.x == 0) {
        unsigned d = atomicAdd(&g_done_blocks, 1u);
        if (d == gridDim.x - 1u) {
            g_slow_count = 0u;
            g_done_blocks = 0u;
        }
    }
}

extern "C" void kernel_launch(void* const* d_in, const int* in_sizes, int n_in,
                              void* d_out, int out_size)
{
    const float* y = (const float*)d_in[0];
    const float* W = (const float*)d_in[1];
    const float* V = (const float*)d_in[2];
    int B = in_sizes[0] / 8;   // y is [B, 8]

    int threads = 256;
    int blocks = (B + threads - 1) / threads;
    rcpl_fast<<<blocks, threads>>>((const float4*)y, W, V, (float4*)d_out, B);
    rcpl_slow<<<64, 128>>>((const float4*)y, W, V, (float4*)d_out);
}